// round 1
// baseline (speedup 1.0000x reference)
#include <cuda_runtime.h>
#include <cuda_bf16.h>

// ---------------------------------------------------------------------------
// HierarchicalGNN: dept GAT(128->4x64 concat)+ReLU -> GAT(256->64) ->
//   gather/concat -> emp GAT(192->4x64 concat)+ReLU -> GAT(256->32) -> log_softmax
// ---------------------------------------------------------------------------

#define N_D 2000
#define E_D 32000
#define N_E 50000
#define E_E 800000
#define IN_F 128
#define DHC 64
#define EHC 64
#define OUTC 32
#define HEADS 4
#define CAT_F (IN_F + DHC)   // 192

// ------------------------- scratch (device globals) -------------------------
__device__ float g_d_h1 [N_D * HEADS * DHC];
__device__ float g_d_as1[N_D * HEADS];
__device__ float g_d_ad1[N_D * HEADS];
__device__ float g_d_s1 [N_D * HEADS];
__device__ float g_d_exp1[(E_D + N_D) * HEADS];
__device__ float g_d_out1[N_D * HEADS * DHC];
__device__ float g_d_h2 [N_D * DHC];
__device__ float g_d_as2[N_D];
__device__ float g_d_ad2[N_D];
__device__ float g_d_s2 [N_D];
__device__ float g_d_exp2[E_D + N_D];
__device__ float g_d_out2[N_D * DHC];

__device__ float g_e_in [N_E * CAT_F];
__device__ float g_e_h1 [N_E * HEADS * EHC];
__device__ float g_e_as1[N_E * HEADS];
__device__ float g_e_ad1[N_E * HEADS];
__device__ float g_e_s1 [N_E * HEADS];
__device__ float g_e_exp1[(E_E + N_E) * HEADS];
__device__ float g_e_out1[N_E * HEADS * EHC];
__device__ float g_e_h2 [N_E * OUTC];
__device__ float g_e_as2[N_E];
__device__ float g_e_ad2[N_E];
__device__ float g_e_s2 [N_E];
__device__ float g_e_exp2[E_E + N_E];
__device__ float g_e_out2[N_E * OUTC];

// ------------------------------- GEMM 64x64x16 ------------------------------
// C[M,N] = A[M,K] @ B[K,N]; row-major; K % 16 == 0, N % 4 == 0 required.
__global__ void gemm64(const float* __restrict__ A, const float* __restrict__ B,
                       float* __restrict__ C, int M, int N, int K) {
    __shared__ float As[16][64];
    __shared__ float Bs[16][64];
    const int t  = threadIdx.x;          // 256 threads
    const int tx = t & 15;
    const int ty = t >> 4;
    const int rowbase = blockIdx.y * 64;
    const int colbase = blockIdx.x * 64;

    // load maps
    const int ar = t >> 2;               // 0..63
    const int ak = (t & 3) * 4;          // 0,4,8,12
    const int bk = t >> 4;               // 0..15
    const int bc = (t & 15) * 4;         // 0..60

    float acc[4][4] = {};

    for (int k0 = 0; k0 < K; k0 += 16) {
        float4 av = make_float4(0.f, 0.f, 0.f, 0.f);
        if (rowbase + ar < M)
            av = *(const float4*)&A[(size_t)(rowbase + ar) * K + k0 + ak];
        As[ak + 0][ar] = av.x;
        As[ak + 1][ar] = av.y;
        As[ak + 2][ar] = av.z;
        As[ak + 3][ar] = av.w;

        float4 bv = make_float4(0.f, 0.f, 0.f, 0.f);
        if (colbase + bc < N)
            bv = *(const float4*)&B[(size_t)(k0 + bk) * N + colbase + bc];
        *(float4*)&Bs[bk][bc] = bv;

        __syncthreads();
#pragma unroll
        for (int kk = 0; kk < 16; kk++) {
            float4 a = *(const float4*)&As[kk][ty * 4];
            float4 b = *(const float4*)&Bs[kk][tx * 4];
            acc[0][0] += a.x * b.x; acc[0][1] += a.x * b.y; acc[0][2] += a.x * b.z; acc[0][3] += a.x * b.w;
            acc[1][0] += a.y * b.x; acc[1][1] += a.y * b.y; acc[1][2] += a.y * b.z; acc[1][3] += a.y * b.w;
            acc[2][0] += a.z * b.x; acc[2][1] += a.z * b.y; acc[2][2] += a.z * b.z; acc[2][3] += a.z * b.w;
            acc[3][0] += a.w * b.x; acc[3][1] += a.w * b.y; acc[3][2] += a.w * b.z; acc[3][3] += a.w * b.w;
        }
        __syncthreads();
    }

#pragma unroll
    for (int i = 0; i < 4; i++) {
        int row = rowbase + ty * 4 + i;
        if (row >= M) continue;
#pragma unroll
        for (int j = 0; j < 4; j++) {
            int col = colbase + tx * 4 + j;
            if (col < N) C[(size_t)row * N + col] = acc[i][j];
        }
    }
}

// ----------------------- attention logits per node --------------------------
// one warp per node; as[n,h] = <h[n,h,:], a_src[h,:]>, ad likewise
__global__ void alpha_warp(const float* __restrict__ h,
                           const float* __restrict__ a_src,
                           const float* __restrict__ a_dst,
                           float* __restrict__ as_out, float* __restrict__ ad_out,
                           int N, int H, int C) {
    int warp = (blockIdx.x * blockDim.x + threadIdx.x) >> 5;
    int lane = threadIdx.x & 31;
    if (warp >= N) return;
    const float* hr = h + (size_t)warp * H * C;
    for (int hh = 0; hh < H; hh++) {
        float s1 = 0.f, s2 = 0.f;
        for (int c = lane; c < C; c += 32) {
            float v = hr[hh * C + c];
            s1 += v * a_src[hh * C + c];
            s2 += v * a_dst[hh * C + c];
        }
#pragma unroll
        for (int o = 16; o; o >>= 1) {
            s1 += __shfl_xor_sync(0xffffffffu, s1, o);
            s2 += __shfl_xor_sync(0xffffffffu, s2, o);
        }
        if (lane == 0) {
            as_out[warp * H + hh] = s1;
            ad_out[warp * H + hh] = s2;
        }
    }
}

// -------------------- edge pass 1: exp(leaky_relu) + segment sum ------------
__global__ void edge_num(const int* __restrict__ ei, int E, int N, int H,
                         const float* __restrict__ as_in, const float* __restrict__ ad_in,
                         float* __restrict__ expbuf, float* __restrict__ s) {
    int t = blockIdx.x * blockDim.x + threadIdx.x;
    int total = (E + N) * H;
    if (t >= total) return;
    int e = t / H, hh = t - e * H;
    int src, dst;
    if (e < E) { src = ei[e]; dst = ei[E + e]; }
    else       { src = dst = e - E; }
    float v = as_in[src * H + hh] + ad_in[dst * H + hh];
    v = (v > 0.f) ? v : 0.2f * v;          // leaky relu
    float ex = __expf(v);                   // shift-invariant softmax (logits small)
    expbuf[t] = ex;
    atomicAdd(&s[dst * H + hh], ex);
}

// -------------------- edge pass 2: weighted scatter-add ----------------------
// thread per (edge, channel); loops over heads
__global__ void edge_agg(const int* __restrict__ ei, int E, int N, int H, int C,
                         const float* __restrict__ hbuf, const float* __restrict__ expbuf,
                         const float* __restrict__ s, float* __restrict__ out) {
    int t = blockIdx.x * blockDim.x + threadIdx.x;
    int total = (E + N) * C;
    if (t >= total) return;
    int c = t % C;
    int e = t / C;
    int src, dst;
    if (e < E) { src = ei[e]; dst = ei[E + e]; }
    else       { src = dst = e - E; }
    for (int hh = 0; hh < H; hh++) {
        float alpha = expbuf[e * H + hh] / (s[dst * H + hh] + 1e-16f);
        float val   = hbuf[((size_t)src * H + hh) * C + c] * alpha;
        atomicAdd(&out[((size_t)dst * H + hh) * C + c], val);
    }
}

// ------------------------------ bias (+relu) --------------------------------
__global__ void bias_act(float* __restrict__ buf, const float* __restrict__ b,
                         int N, int F, int relu) {
    int t = blockIdx.x * blockDim.x + threadIdx.x;
    if (t >= N * F) return;
    float v = buf[t] + b[t % F];
    buf[t] = relu ? fmaxf(v, 0.f) : v;
}

// ------------------------------ concat gather -------------------------------
__global__ void concat_kernel(const float* __restrict__ emp_x,
                              const float* __restrict__ d,
                              const int* __restrict__ dept_idx,
                              float* __restrict__ out) {
    int t = blockIdx.x * blockDim.x + threadIdx.x;
    if (t >= N_E * CAT_F) return;
    int n = t / CAT_F, f = t - n * CAT_F;
    out[t] = (f < IN_F) ? emp_x[(size_t)n * IN_F + f]
                        : d[(size_t)dept_idx[n] * DHC + (f - IN_F)];
}

// --------------------------- log_softmax (C=32) ------------------------------
__global__ void logsoftmax32(const float* __restrict__ in, const float* __restrict__ b,
                             float* __restrict__ out) {
    int row  = (blockIdx.x * blockDim.x + threadIdx.x) >> 5;
    int lane = threadIdx.x & 31;
    if (row >= N_E) return;
    float v = in[(size_t)row * 32 + lane] + b[lane];
    float m = v;
#pragma unroll
    for (int o = 16; o; o >>= 1) m = fmaxf(m, __shfl_xor_sync(0xffffffffu, m, o));
    float ex = __expf(v - m);
    float s  = ex;
#pragma unroll
    for (int o = 16; o; o >>= 1) s += __shfl_xor_sync(0xffffffffu, s, o);
    out[(size_t)row * 32 + lane] = (v - m) - logf(s);
}

// --------------------------------- host side --------------------------------
static inline float* sym(const void* s) {
    void* p = nullptr;
    cudaGetSymbolAddress(&p, s);
    return (float*)p;
}
static inline int cdiv(int a, int b) { return (a + b - 1) / b; }

extern "C" void kernel_launch(void* const* d_in, const int* in_sizes, int n_in,
                              void* d_out, int out_size) {
    const float* dept_x  = (const float*)d_in[0];
    const int*   dept_ei = (const int*)  d_in[1];
    const float* emp_x   = (const float*)d_in[2];
    const int*   emp_ei  = (const int*)  d_in[3];
    const int*   dept_ix = (const int*)  d_in[4];
    const float* W_d1    = (const float*)d_in[5];
    const float* as_d1   = (const float*)d_in[6];
    const float* ad_d1   = (const float*)d_in[7];
    const float* b_d1    = (const float*)d_in[8];
    const float* W_d2    = (const float*)d_in[9];
    const float* as_d2   = (const float*)d_in[10];
    const float* ad_d2   = (const float*)d_in[11];
    const float* b_d2    = (const float*)d_in[12];
    const float* W_e1    = (const float*)d_in[13];
    const float* as_e1   = (const float*)d_in[14];
    const float* ad_e1   = (const float*)d_in[15];
    const float* b_e1    = (const float*)d_in[16];
    const float* W_e2    = (const float*)d_in[17];
    const float* as_e2   = (const float*)d_in[18];
    const float* ad_e2   = (const float*)d_in[19];
    const float* b_e2    = (const float*)d_in[20];
    float* out = (float*)d_out;

    float *p_d_h1 = sym(g_d_h1), *p_d_as1 = sym(g_d_as1), *p_d_ad1 = sym(g_d_ad1);
    float *p_d_s1 = sym(g_d_s1), *p_d_exp1 = sym(g_d_exp1), *p_d_out1 = sym(g_d_out1);
    float *p_d_h2 = sym(g_d_h2), *p_d_as2 = sym(g_d_as2), *p_d_ad2 = sym(g_d_ad2);
    float *p_d_s2 = sym(g_d_s2), *p_d_exp2 = sym(g_d_exp2), *p_d_out2 = sym(g_d_out2);
    float *p_e_in = sym(g_e_in), *p_e_h1 = sym(g_e_h1), *p_e_as1 = sym(g_e_as1);
    float *p_e_ad1 = sym(g_e_ad1), *p_e_s1 = sym(g_e_s1), *p_e_exp1 = sym(g_e_exp1);
    float *p_e_out1 = sym(g_e_out1), *p_e_h2 = sym(g_e_h2), *p_e_as2 = sym(g_e_as2);
    float *p_e_ad2 = sym(g_e_ad2), *p_e_s2 = sym(g_e_s2), *p_e_exp2 = sym(g_e_exp2);
    float *p_e_out2 = sym(g_e_out2);

    const int TB = 256;

    // zero accumulators
    cudaMemsetAsync(p_d_s1,   0, sizeof(float) * N_D * HEADS);
    cudaMemsetAsync(p_d_out1, 0, sizeof(float) * N_D * HEADS * DHC);
    cudaMemsetAsync(p_d_s2,   0, sizeof(float) * N_D);
    cudaMemsetAsync(p_d_out2, 0, sizeof(float) * N_D * DHC);
    cudaMemsetAsync(p_e_s1,   0, sizeof(float) * N_E * HEADS);
    cudaMemsetAsync(p_e_out1, 0, sizeof(float) * N_E * HEADS * EHC);
    cudaMemsetAsync(p_e_s2,   0, sizeof(float) * N_E);
    cudaMemsetAsync(p_e_out2, 0, sizeof(float) * N_E * OUTC);

    // ============ dept layer 1: GAT(128 -> 4x64, concat) + ReLU ============
    {
        dim3 g(cdiv(HEADS * DHC, 64), cdiv(N_D, 64));
        gemm64<<<g, 256>>>(dept_x, W_d1, p_d_h1, N_D, HEADS * DHC, IN_F);
        alpha_warp<<<cdiv(N_D * 32, TB), TB>>>(p_d_h1, as_d1, ad_d1, p_d_as1, p_d_ad1, N_D, HEADS, DHC);
        int EH1 = (E_D + N_D) * HEADS;
        edge_num<<<cdiv(EH1, TB), TB>>>(dept_ei, E_D, N_D, HEADS, p_d_as1, p_d_ad1, p_d_exp1, p_d_s1);
        int AG1 = (E_D + N_D) * DHC;
        edge_agg<<<cdiv(AG1, TB), TB>>>(dept_ei, E_D, N_D, HEADS, DHC, p_d_h1, p_d_exp1, p_d_s1, p_d_out1);
        bias_act<<<cdiv(N_D * HEADS * DHC, TB), TB>>>(p_d_out1, b_d1, N_D, HEADS * DHC, 1);
    }
    // ============ dept layer 2: GAT(256 -> 64, heads=1) ============
    {
        dim3 g(cdiv(DHC, 64), cdiv(N_D, 64));
        gemm64<<<g, 256>>>(p_d_out1, W_d2, p_d_h2, N_D, DHC, HEADS * DHC);
        alpha_warp<<<cdiv(N_D * 32, TB), TB>>>(p_d_h2, as_d2, ad_d2, p_d_as2, p_d_ad2, N_D, 1, DHC);
        int EH2 = (E_D + N_D);
        edge_num<<<cdiv(EH2, TB), TB>>>(dept_ei, E_D, N_D, 1, p_d_as2, p_d_ad2, p_d_exp2, p_d_s2);
        int AG2 = (E_D + N_D) * DHC;
        edge_agg<<<cdiv(AG2, TB), TB>>>(dept_ei, E_D, N_D, 1, DHC, p_d_h2, p_d_exp2, p_d_s2, p_d_out2);
        bias_act<<<cdiv(N_D * DHC, TB), TB>>>(p_d_out2, b_d2, N_D, DHC, 0);
    }
    // ============ hierarchical fusion: concat(emp_x, d[dept_idx]) ============
    concat_kernel<<<cdiv(N_E * CAT_F, TB), TB>>>(emp_x, p_d_out2, dept_ix, p_e_in);

    // ============ emp layer 1: GAT(192 -> 4x64, concat) + ReLU ============
    {
        dim3 g(cdiv(HEADS * EHC, 64), cdiv(N_E, 64));
        gemm64<<<g, 256>>>(p_e_in, W_e1, p_e_h1, N_E, HEADS * EHC, CAT_F);
        alpha_warp<<<cdiv(N_E * 32, TB), TB>>>(p_e_h1, as_e1, ad_e1, p_e_as1, p_e_ad1, N_E, HEADS, EHC);
        int EH1 = (E_E + N_E) * HEADS;
        edge_num<<<cdiv(EH1, TB), TB>>>(emp_ei, E_E, N_E, HEADS, p_e_as1, p_e_ad1, p_e_exp1, p_e_s1);
        int AG1 = (E_E + N_E) * EHC;
        edge_agg<<<cdiv(AG1, TB), TB>>>(emp_ei, E_E, N_E, HEADS, EHC, p_e_h1, p_e_exp1, p_e_s1, p_e_out1);
        bias_act<<<cdiv(N_E * HEADS * EHC, TB), TB>>>(p_e_out1, b_e1, N_E, HEADS * EHC, 1);
    }
    // ============ emp layer 2: GAT(256 -> 32, heads=1) + log_softmax ============
    {
        dim3 g(cdiv(OUTC, 64), cdiv(N_E, 64));
        gemm64<<<g, 256>>>(p_e_out1, W_e2, p_e_h2, N_E, OUTC, HEADS * EHC);
        alpha_warp<<<cdiv(N_E * 32, TB), TB>>>(p_e_h2, as_e2, ad_e2, p_e_as2, p_e_ad2, N_E, 1, OUTC);
        int EH2 = (E_E + N_E);
        edge_num<<<cdiv(EH2, TB), TB>>>(emp_ei, E_E, N_E, 1, p_e_as2, p_e_ad2, p_e_exp2, p_e_s2);
        int AG2 = (E_E + N_E) * OUTC;
        edge_agg<<<cdiv(AG2, TB), TB>>>(emp_ei, E_E, N_E, 1, OUTC, p_e_h2, p_e_exp2, p_e_s2, p_e_out2);
        logsoftmax32<<<cdiv(N_E * 32, TB), TB>>>(p_e_out2, b_e2, out);
    }
}

// round 2
// speedup vs baseline: 2.6732x; 2.6732x over previous
#include <cuda_runtime.h>
#include <cuda_bf16.h>

#define N_D 2000
#define E_D 32000
#define N_E 50000
#define E_E 800000
#define IN_F 128
#define DHC 64
#define EHC 64
#define OUTC 32
#define HEADS 4
#define CAT_F (IN_F + DHC)   // 192

// ------------------------- scratch (device globals) -------------------------
__device__ float g_d_h1 [N_D * HEADS * DHC];
__device__ float g_d_as1[N_D * HEADS];
__device__ float g_d_ad1[N_D * HEADS];
__device__ float g_d_out1[N_D * HEADS * DHC];
__device__ float g_d_h2 [N_D * DHC];
__device__ float g_d_as2[N_D];
__device__ float g_d_ad2[N_D];
__device__ float g_d_out2[N_D * DHC];

__device__ float g_e_in [N_E * CAT_F];
__device__ float g_e_h1 [N_E * HEADS * EHC];
__device__ float g_e_as1[N_E * HEADS];
__device__ float g_e_ad1[N_E * HEADS];
__device__ float g_e_out1[N_E * HEADS * EHC];
__device__ float g_e_h2 [N_E * OUTC];
__device__ float g_e_as2[N_E];
__device__ float g_e_ad2[N_E];

// CSR scratch
__device__ int g_deg_d [N_D];
__device__ int g_cur_d [N_D];
__device__ int g_row_d [N_D + 1];
__device__ int g_colv_d[E_D + N_D];
__device__ int g_bs_d  [256];
__device__ int g_deg_e [N_E];
__device__ int g_cur_e [N_E];
__device__ int g_row_e [N_E + 1];
__device__ int g_colv_e[E_E + N_E];
__device__ int g_bs_e  [256];

static inline int cdiv(int a, int b) { return (a + b - 1) / b; }

// =============================== CSR build ==================================
__global__ void deg_count(const int* __restrict__ ei, int E, int* __restrict__ deg) {
    int t = blockIdx.x * blockDim.x + threadIdx.x;
    if (t < E) atomicAdd(&deg[ei[E + t]], 1);
}

// per-256-block sums of (deg[i]+1)
__global__ void block_sum(const int* __restrict__ deg, int N, int* __restrict__ bsum) {
    __shared__ int sh[256];
    int i = blockIdx.x * 256 + threadIdx.x;
    sh[threadIdx.x] = (i < N) ? (deg[i] + 1) : 0;
    __syncthreads();
    for (int off = 128; off; off >>= 1) {
        if (threadIdx.x < off) sh[threadIdx.x] += sh[threadIdx.x + off];
        __syncthreads();
    }
    if (threadIdx.x == 0) bsum[blockIdx.x] = sh[0];
}

__global__ void scan_bsums(int* __restrict__ bsum, int nb, int* __restrict__ rowptr,
                           int total, int N) {
    if (threadIdx.x == 0) {
        int acc = 0;
        for (int i = 0; i < nb; i++) { int v = bsum[i]; bsum[i] = acc; acc += v; }
        rowptr[N] = total;
    }
}

__global__ void scan_final(const int* __restrict__ deg, const int* __restrict__ bsum,
                           int N, int* __restrict__ rowptr) {
    __shared__ int sh[256];
    int i = blockIdx.x * 256 + threadIdx.x;
    int v = (i < N) ? (deg[i] + 1) : 0;
    sh[threadIdx.x] = v;
    __syncthreads();
    // Hillis-Steele inclusive scan
    for (int off = 1; off < 256; off <<= 1) {
        int x = (threadIdx.x >= off) ? sh[threadIdx.x - off] : 0;
        __syncthreads();
        sh[threadIdx.x] += x;
        __syncthreads();
    }
    if (i < N) rowptr[i] = bsum[blockIdx.x] + sh[threadIdx.x] - v;
}

__global__ void fill_csr(const int* __restrict__ ei, int E, int N,
                         const int* __restrict__ rowptr, int* __restrict__ cur,
                         int* __restrict__ colv) {
    int t = blockIdx.x * blockDim.x + threadIdx.x;
    if (t >= E + N) return;
    int src, dst;
    if (t < E) { src = ei[t]; dst = ei[E + t]; }
    else       { src = dst = t - E; }
    int pos = rowptr[dst] + atomicAdd(&cur[dst], 1);
    colv[pos] = src;
}

// ============================ GEMM 128x128x16 ===============================
// C[M,N]=A@B; 256 threads, 8x8 per thread. Requires N%128==0, K%16==0, K%4==0.
__global__ void gemm128(const float* __restrict__ A, const float* __restrict__ B,
                        float* __restrict__ C, int M, int N, int K) {
    __shared__ float As[16][128];
    __shared__ float Bs[16][128];
    const int t  = threadIdx.x;
    const int tx = t & 15;            // 0..15
    const int ty = t >> 4;            // 0..15
    const int rowbase = blockIdx.y * 128;
    const int colbase = blockIdx.x * 128;

    const int ar = t >> 2;            // 0..63 (rows ar, ar+64)
    const int ak = (t & 3) * 4;       // 0,4,8,12
    const int bk = t >> 5;            // 0..7 (k rows bk, bk+8)
    const int bc = (t & 31) * 4;      // 0..124

    float acc[8][8] = {};

    for (int k0 = 0; k0 < K; k0 += 16) {
#pragma unroll
        for (int half = 0; half < 2; half++) {
            int r = ar + half * 64;
            float4 av = make_float4(0.f, 0.f, 0.f, 0.f);
            if (rowbase + r < M)
                av = *(const float4*)&A[(size_t)(rowbase + r) * K + k0 + ak];
            As[ak + 0][r] = av.x;
            As[ak + 1][r] = av.y;
            As[ak + 2][r] = av.z;
            As[ak + 3][r] = av.w;
        }
#pragma unroll
        for (int half = 0; half < 2; half++) {
            int kr = bk + half * 8;
            float4 bv = *(const float4*)&B[(size_t)(k0 + kr) * N + colbase + bc];
            *(float4*)&Bs[kr][bc] = bv;
        }
        __syncthreads();
#pragma unroll
        for (int kk = 0; kk < 16; kk++) {
            float4 a0 = *(const float4*)&As[kk][ty * 8];
            float4 a1 = *(const float4*)&As[kk][ty * 8 + 4];
            float4 b0 = *(const float4*)&Bs[kk][tx * 8];
            float4 b1 = *(const float4*)&Bs[kk][tx * 8 + 4];
            float av[8] = {a0.x, a0.y, a0.z, a0.w, a1.x, a1.y, a1.z, a1.w};
            float bv[8] = {b0.x, b0.y, b0.z, b0.w, b1.x, b1.y, b1.z, b1.w};
#pragma unroll
            for (int i = 0; i < 8; i++)
#pragma unroll
                for (int j = 0; j < 8; j++)
                    acc[i][j] += av[i] * bv[j];
        }
        __syncthreads();
    }

#pragma unroll
    for (int i = 0; i < 8; i++) {
        int row = rowbase + ty * 8 + i;
        if (row >= M) continue;
        float4 v0 = make_float4(acc[i][0], acc[i][1], acc[i][2], acc[i][3]);
        float4 v1 = make_float4(acc[i][4], acc[i][5], acc[i][6], acc[i][7]);
        *(float4*)&C[(size_t)row * N + colbase + tx * 8]     = v0;
        *(float4*)&C[(size_t)row * N + colbase + tx * 8 + 4] = v1;
    }
}

// ============================ GEMM 64x64x16 (small N) =======================
__global__ void gemm64(const float* __restrict__ A, const float* __restrict__ B,
                       float* __restrict__ C, int M, int N, int K) {
    __shared__ float As[16][64];
    __shared__ float Bs[16][64];
    const int t  = threadIdx.x;
    const int tx = t & 15;
    const int ty = t >> 4;
    const int rowbase = blockIdx.y * 64;
    const int colbase = blockIdx.x * 64;
    const int ar = t >> 2;
    const int ak = (t & 3) * 4;
    const int bk = t >> 4;
    const int bc = (t & 15) * 4;

    float acc[4][4] = {};
    for (int k0 = 0; k0 < K; k0 += 16) {
        float4 av = make_float4(0.f, 0.f, 0.f, 0.f);
        if (rowbase + ar < M)
            av = *(const float4*)&A[(size_t)(rowbase + ar) * K + k0 + ak];
        As[ak + 0][ar] = av.x; As[ak + 1][ar] = av.y;
        As[ak + 2][ar] = av.z; As[ak + 3][ar] = av.w;
        float4 bv = make_float4(0.f, 0.f, 0.f, 0.f);
        if (colbase + bc < N)
            bv = *(const float4*)&B[(size_t)(k0 + bk) * N + colbase + bc];
        *(float4*)&Bs[bk][bc] = bv;
        __syncthreads();
#pragma unroll
        for (int kk = 0; kk < 16; kk++) {
            float4 a = *(const float4*)&As[kk][ty * 4];
            float4 b = *(const float4*)&Bs[kk][tx * 4];
            acc[0][0] += a.x * b.x; acc[0][1] += a.x * b.y; acc[0][2] += a.x * b.z; acc[0][3] += a.x * b.w;
            acc[1][0] += a.y * b.x; acc[1][1] += a.y * b.y; acc[1][2] += a.y * b.z; acc[1][3] += a.y * b.w;
            acc[2][0] += a.z * b.x; acc[2][1] += a.z * b.y; acc[2][2] += a.z * b.z; acc[2][3] += a.z * b.w;
            acc[3][0] += a.w * b.x; acc[3][1] += a.w * b.y; acc[3][2] += a.w * b.z; acc[3][3] += a.w * b.w;
        }
        __syncthreads();
    }
#pragma unroll
    for (int i = 0; i < 4; i++) {
        int row = rowbase + ty * 4 + i;
        if (row >= M) continue;
#pragma unroll
        for (int j = 0; j < 4; j++) {
            int col = colbase + tx * 4 + j;
            if (col < N) C[(size_t)row * N + col] = acc[i][j];
        }
    }
}

// ----------------------- attention logits per node --------------------------
__global__ void alpha_warp(const float* __restrict__ h,
                           const float* __restrict__ a_src,
                           const float* __restrict__ a_dst,
                           float* __restrict__ as_out, float* __restrict__ ad_out,
                           int N, int H, int C) {
    int warp = (blockIdx.x * blockDim.x + threadIdx.x) >> 5;
    int lane = threadIdx.x & 31;
    if (warp >= N) return;
    const float* hr = h + (size_t)warp * H * C;
    for (int hh = 0; hh < H; hh++) {
        float s1 = 0.f, s2 = 0.f;
        for (int c = lane; c < C; c += 32) {
            float v = hr[hh * C + c];
            s1 += v * a_src[hh * C + c];
            s2 += v * a_dst[hh * C + c];
        }
#pragma unroll
        for (int o = 16; o; o >>= 1) {
            s1 += __shfl_xor_sync(0xffffffffu, s1, o);
            s2 += __shfl_xor_sync(0xffffffffu, s2, o);
        }
        if (lane == 0) {
            as_out[warp * H + hh] = s1;
            ad_out[warp * H + hh] = s2;
        }
    }
}

// ===================== fused gather: softmax + aggregate =====================
// one warp per (node, head). ACT: 0 = bias, 1 = bias+relu, 2 = bias+log_softmax
// (ACT==2 requires H==1, C==32).
template<int H, int C, int ACT>
__global__ void gat_gather(const int* __restrict__ rowptr, const int* __restrict__ colv,
                           const float* __restrict__ as_, const float* __restrict__ ad_,
                           const float* __restrict__ h, const float* __restrict__ bias,
                           float* __restrict__ outbuf, int N) {
    int gw   = (blockIdx.x * blockDim.x + threadIdx.x) >> 5;
    int lane = threadIdx.x & 31;
    if (gw >= N * H) return;
    int n  = gw / H;
    int hh = gw - n * H;

    int start = rowptr[n], end = rowptr[n + 1];
    float adv = ad_[n * H + hh];

    // pass 1: softmax denominator
    float ssum = 0.f;
    for (int j = start + lane; j < end; j += 32) {
        float v = as_[colv[j] * H + hh] + adv;
        v = (v > 0.f) ? v : 0.2f * v;
        ssum += __expf(v);
    }
#pragma unroll
    for (int o = 16; o; o >>= 1) ssum += __shfl_xor_sync(0xffffffffu, ssum, o);
    float inv = 1.f / (ssum + 1e-16f);

    // pass 2: weighted aggregation (lane owns channel lane [, lane+32])
    float acc0 = 0.f, acc1 = 0.f;
    for (int base = start; base < end; base += 32) {
        int jj = base + lane;
        int srcv = 0; float al = 0.f;
        if (jj < end) {
            srcv = colv[jj];
            float v = as_[srcv * H + hh] + adv;
            v = (v > 0.f) ? v : 0.2f * v;
            al = __expf(v);
        }
        int kmax = min(32, end - base);
        for (int k = 0; k < kmax; k++) {
            int   s_k = __shfl_sync(0xffffffffu, srcv, k);
            float a_k = __shfl_sync(0xffffffffu, al,   k);
            const float* hp = h + (size_t)s_k * (H * C) + hh * C;
            acc0 += a_k * hp[lane];
            if (C == 64) acc1 += a_k * hp[lane + 32];
        }
    }

    if (ACT == 2) {
        // fused bias + log_softmax over 32 channels
        float v = acc0 * inv + bias[lane];
        float m = v;
#pragma unroll
        for (int o = 16; o; o >>= 1) m = fmaxf(m, __shfl_xor_sync(0xffffffffu, m, o));
        float ex = __expf(v - m);
        float se = ex;
#pragma unroll
        for (int o = 16; o; o >>= 1) se += __shfl_xor_sync(0xffffffffu, se, o);
        outbuf[(size_t)n * 32 + lane] = (v - m) - logf(se);
    } else {
        size_t idx = (size_t)n * (H * C) + hh * C;
        float v0 = acc0 * inv + bias[hh * C + lane];
        if (ACT == 1) v0 = fmaxf(v0, 0.f);
        outbuf[idx + lane] = v0;
        if (C == 64) {
            float v1 = acc1 * inv + bias[hh * C + lane + 32];
            if (ACT == 1) v1 = fmaxf(v1, 0.f);
            outbuf[idx + lane + 32] = v1;
        }
    }
}

// ------------------------------ concat gather (float4) ----------------------
__global__ void concat_kernel(const float* __restrict__ emp_x,
                              const float* __restrict__ d,
                              const int* __restrict__ dept_idx,
                              float* __restrict__ out) {
    int t = blockIdx.x * blockDim.x + threadIdx.x;    // over N_E * 48 float4s
    if (t >= N_E * (CAT_F / 4)) return;
    int n = t / (CAT_F / 4), f4 = t - n * (CAT_F / 4);
    float4 v;
    if (f4 < IN_F / 4) v = *(const float4*)&emp_x[(size_t)n * IN_F + f4 * 4];
    else               v = *(const float4*)&d[(size_t)dept_idx[n] * DHC + (f4 - IN_F / 4) * 4];
    *(float4*)&out[(size_t)n * CAT_F + f4 * 4] = v;
}

// --------------------------------- host side --------------------------------
template<typename T>
static inline T* sym(const void* s) {
    void* p = nullptr;
    cudaGetSymbolAddress(&p, s);
    return (T*)p;
}

extern "C" void kernel_launch(void* const* d_in, const int* in_sizes, int n_in,
                              void* d_out, int out_size) {
    const float* dept_x  = (const float*)d_in[0];
    const int*   dept_ei = (const int*)  d_in[1];
    const float* emp_x   = (const float*)d_in[2];
    const int*   emp_ei  = (const int*)  d_in[3];
    const int*   dept_ix = (const int*)  d_in[4];
    const float* W_d1    = (const float*)d_in[5];
    const float* as_d1   = (const float*)d_in[6];
    const float* ad_d1   = (const float*)d_in[7];
    const float* b_d1    = (const float*)d_in[8];
    const float* W_d2    = (const float*)d_in[9];
    const float* as_d2   = (const float*)d_in[10];
    const float* ad_d2   = (const float*)d_in[11];
    const float* b_d2    = (const float*)d_in[12];
    const float* W_e1    = (const float*)d_in[13];
    const float* as_e1   = (const float*)d_in[14];
    const float* ad_e1   = (const float*)d_in[15];
    const float* b_e1    = (const float*)d_in[16];
    const float* W_e2    = (const float*)d_in[17];
    const float* as_e2   = (const float*)d_in[18];
    const float* ad_e2   = (const float*)d_in[19];
    const float* b_e2    = (const float*)d_in[20];
    float* out = (float*)d_out;

    float *p_d_h1 = sym<float>(g_d_h1), *p_d_as1 = sym<float>(g_d_as1), *p_d_ad1 = sym<float>(g_d_ad1);
    float *p_d_out1 = sym<float>(g_d_out1), *p_d_h2 = sym<float>(g_d_h2);
    float *p_d_as2 = sym<float>(g_d_as2), *p_d_ad2 = sym<float>(g_d_ad2), *p_d_out2 = sym<float>(g_d_out2);
    float *p_e_in = sym<float>(g_e_in), *p_e_h1 = sym<float>(g_e_h1);
    float *p_e_as1 = sym<float>(g_e_as1), *p_e_ad1 = sym<float>(g_e_ad1), *p_e_out1 = sym<float>(g_e_out1);
    float *p_e_h2 = sym<float>(g_e_h2), *p_e_as2 = sym<float>(g_e_as2), *p_e_ad2 = sym<float>(g_e_ad2);

    int *deg_d = sym<int>(g_deg_d), *cur_d = sym<int>(g_cur_d), *row_d = sym<int>(g_row_d);
    int *col_d = sym<int>(g_colv_d), *bs_d = sym<int>(g_bs_d);
    int *deg_e = sym<int>(g_deg_e), *cur_e = sym<int>(g_cur_e), *row_e = sym<int>(g_row_e);
    int *col_e = sym<int>(g_colv_e), *bs_e = sym<int>(g_bs_e);

    const int TB = 256;

    // zero CSR counters
    cudaMemsetAsync(deg_d, 0, sizeof(int) * N_D);
    cudaMemsetAsync(cur_d, 0, sizeof(int) * N_D);
    cudaMemsetAsync(deg_e, 0, sizeof(int) * N_E);
    cudaMemsetAsync(cur_e, 0, sizeof(int) * N_E);

    // ---- build CSR: dept graph ----
    {
        int nb = cdiv(N_D, 256);
        deg_count<<<cdiv(E_D, TB), TB>>>(dept_ei, E_D, deg_d);
        block_sum<<<nb, 256>>>(deg_d, N_D, bs_d);
        scan_bsums<<<1, 32>>>(bs_d, nb, row_d, E_D + N_D, N_D);
        scan_final<<<nb, 256>>>(deg_d, bs_d, N_D, row_d);
        fill_csr<<<cdiv(E_D + N_D, TB), TB>>>(dept_ei, E_D, N_D, row_d, cur_d, col_d);
    }
    // ---- build CSR: emp graph ----
    {
        int nb = cdiv(N_E, 256);
        deg_count<<<cdiv(E_E, TB), TB>>>(emp_ei, E_E, deg_e);
        block_sum<<<nb, 256>>>(deg_e, N_E, bs_e);
        scan_bsums<<<1, 32>>>(bs_e, nb, row_e, E_E + N_E, N_E);
        scan_final<<<nb, 256>>>(deg_e, bs_e, N_E, row_e);
        fill_csr<<<cdiv(E_E + N_E, TB), TB>>>(emp_ei, E_E, N_E, row_e, cur_e, col_e);
    }

    // ============ dept layer 1: GAT(128 -> 4x64, concat) + ReLU ============
    {
        dim3 g(cdiv(HEADS * DHC, 128), cdiv(N_D, 128));
        gemm128<<<g, 256>>>(dept_x, W_d1, p_d_h1, N_D, HEADS * DHC, IN_F);
        alpha_warp<<<cdiv(N_D * 32, TB), TB>>>(p_d_h1, as_d1, ad_d1, p_d_as1, p_d_ad1, N_D, HEADS, DHC);
        gat_gather<HEADS, DHC, 1><<<cdiv(N_D * HEADS * 32, TB), TB>>>(
            row_d, col_d, p_d_as1, p_d_ad1, p_d_h1, b_d1, p_d_out1, N_D);
    }
    // ============ dept layer 2: GAT(256 -> 64, heads=1) ============
    {
        dim3 g(cdiv(DHC, 64), cdiv(N_D, 64));
        gemm64<<<g, 256>>>(p_d_out1, W_d2, p_d_h2, N_D, DHC, HEADS * DHC);
        alpha_warp<<<cdiv(N_D * 32, TB), TB>>>(p_d_h2, as_d2, ad_d2, p_d_as2, p_d_ad2, N_D, 1, DHC);
        gat_gather<1, DHC, 0><<<cdiv(N_D * 32, TB), TB>>>(
            row_d, col_d, p_d_as2, p_d_ad2, p_d_h2, b_d2, p_d_out2, N_D);
    }
    // ============ hierarchical fusion ============
    concat_kernel<<<cdiv(N_E * (CAT_F / 4), TB), TB>>>(emp_x, p_d_out2, dept_ix, p_e_in);

    // ============ emp layer 1: GAT(192 -> 4x64, concat) + ReLU ============
    {
        dim3 g(cdiv(HEADS * EHC, 128), cdiv(N_E, 128));
        gemm128<<<g, 256>>>(p_e_in, W_e1, p_e_h1, N_E, HEADS * EHC, CAT_F);
        alpha_warp<<<cdiv(N_E * 32, TB), TB>>>(p_e_h1, as_e1, ad_e1, p_e_as1, p_e_ad1, N_E, HEADS, EHC);
        gat_gather<HEADS, EHC, 1><<<cdiv(N_E * HEADS * 32, TB), TB>>>(
            row_e, col_e, p_e_as1, p_e_ad1, p_e_h1, b_e1, p_e_out1, N_E);
    }
    // ============ emp layer 2: GAT(256 -> 32) + log_softmax ============
    {
        dim3 g(cdiv(OUTC, 64), cdiv(N_E, 64));
        gemm64<<<g, 256>>>(p_e_out1, W_e2, p_e_h2, N_E, OUTC, HEADS * EHC);
        alpha_warp<<<cdiv(N_E * 32, TB), TB>>>(p_e_h2, as_e2, ad_e2, p_e_as2, p_e_ad2, N_E, 1, OUTC);
        gat_gather<1, OUTC, 2><<<cdiv(N_E * 32, TB), TB>>>(
            row_e, col_e, p_e_as2, p_e_ad2, p_e_h2, b_e2, out, N_E);
    }
}

// round 3
// speedup vs baseline: 3.0370x; 1.1361x over previous
#include <cuda_runtime.h>
#include <cuda_bf16.h>

#define N_D 2000
#define E_D 32000
#define N_E 50000
#define E_E 800000
#define IN_F 128
#define DHC 64
#define EHC 64
#define OUTC 32
#define HEADS 4

// ------------------------- scratch (device globals) -------------------------
__device__ float g_d_h1 [N_D * HEADS * DHC];
__device__ float g_d_as1[N_D * HEADS];
__device__ float g_d_ad1[N_D * HEADS];
__device__ float g_d_out1[N_D * HEADS * DHC];
__device__ float g_d_h2 [N_D * DHC];
__device__ float g_d_as2[N_D];
__device__ float g_d_ad2[N_D];
__device__ float g_d_out2[N_D * DHC];
__device__ float g_dproj [N_D * HEADS * EHC];   // d_out2 @ W_e1[128:,:]

__device__ float g_e_h1 [N_E * HEADS * EHC];
__device__ float g_e_as1[N_E * HEADS];
__device__ float g_e_ad1[N_E * HEADS];
__device__ float g_e_out1[N_E * HEADS * EHC];
__device__ float g_e_h2 [N_E * OUTC];
__device__ float g_e_as2[N_E];
__device__ float g_e_ad2[N_E];

// CSR scratch
__device__ int g_deg_d [N_D];
__device__ int g_cur_d [N_D];
__device__ int g_row_d [N_D + 1];
__device__ int g_colv_d[E_D + N_D];
__device__ int g_bs_d  [256];
__device__ int g_deg_e [N_E];
__device__ int g_cur_e [N_E];
__device__ int g_row_e [N_E + 1];
__device__ int g_colv_e[E_E + N_E];
__device__ int g_bs_e  [256];

static inline int cdiv(int a, int b) { return (a + b - 1) / b; }

// =============================== CSR build ==================================
__global__ void deg_count(const int* __restrict__ ei, int E, int* __restrict__ deg) {
    int t = blockIdx.x * blockDim.x + threadIdx.x;
    if (t < E) atomicAdd(&deg[ei[E + t]], 1);
}

__global__ void block_sum(const int* __restrict__ deg, int N, int* __restrict__ bsum) {
    __shared__ int sh[256];
    int i = blockIdx.x * 256 + threadIdx.x;
    sh[threadIdx.x] = (i < N) ? (deg[i] + 1) : 0;
    __syncthreads();
    for (int off = 128; off; off >>= 1) {
        if (threadIdx.x < off) sh[threadIdx.x] += sh[threadIdx.x + off];
        __syncthreads();
    }
    if (threadIdx.x == 0) bsum[blockIdx.x] = sh[0];
}

__global__ void scan_bsums(int* __restrict__ bsum, int nb, int* __restrict__ rowptr,
                           int total, int N) {
    if (threadIdx.x == 0) {
        int acc = 0;
        for (int i = 0; i < nb; i++) { int v = bsum[i]; bsum[i] = acc; acc += v; }
        rowptr[N] = total;
    }
}

__global__ void scan_final(const int* __restrict__ deg, const int* __restrict__ bsum,
                           int N, int* __restrict__ rowptr) {
    __shared__ int sh[256];
    int i = blockIdx.x * 256 + threadIdx.x;
    int v = (i < N) ? (deg[i] + 1) : 0;
    sh[threadIdx.x] = v;
    __syncthreads();
    for (int off = 1; off < 256; off <<= 1) {
        int x = (threadIdx.x >= off) ? sh[threadIdx.x - off] : 0;
        __syncthreads();
        sh[threadIdx.x] += x;
        __syncthreads();
    }
    if (i < N) rowptr[i] = bsum[blockIdx.x] + sh[threadIdx.x] - v;
}

__global__ void fill_csr(const int* __restrict__ ei, int E, int N,
                         const int* __restrict__ rowptr, int* __restrict__ cur,
                         int* __restrict__ colv) {
    int t = blockIdx.x * blockDim.x + threadIdx.x;
    if (t >= E + N) return;
    int src, dst;
    if (t < E) { src = ei[t]; dst = ei[E + t]; }
    else       { src = dst = t - E; }
    int pos = rowptr[dst] + atomicAdd(&cur[dst], 1);
    colv[pos] = src;
}

// ============================ GEMM 128x128x16 ===============================
// C[M,N]=A@B (+ optional gathered row add). 256 threads, 8x8/thread.
// Requires N%128==0, K%16==0.
__global__ void gemm128(const float* __restrict__ A, const float* __restrict__ B,
                        float* __restrict__ C, int M, int N, int K,
                        const float* __restrict__ add, const int* __restrict__ idx) {
    __shared__ float As[16][128];
    __shared__ float Bs[16][128];
    const int t  = threadIdx.x;
    const int tx = t & 15;
    const int ty = t >> 4;
    const int rowbase = blockIdx.y * 128;
    const int colbase = blockIdx.x * 128;

    const int ar = t >> 2;
    const int ak = (t & 3) * 4;
    const int bk = t >> 5;
    const int bc = (t & 31) * 4;

    float acc[8][8] = {};

    for (int k0 = 0; k0 < K; k0 += 16) {
#pragma unroll
        for (int half = 0; half < 2; half++) {
            int r = ar + half * 64;
            float4 av = make_float4(0.f, 0.f, 0.f, 0.f);
            if (rowbase + r < M)
                av = *(const float4*)&A[(size_t)(rowbase + r) * K + k0 + ak];
            As[ak + 0][r] = av.x;
            As[ak + 1][r] = av.y;
            As[ak + 2][r] = av.z;
            As[ak + 3][r] = av.w;
        }
#pragma unroll
        for (int half = 0; half < 2; half++) {
            int kr = bk + half * 8;
            float4 bv = *(const float4*)&B[(size_t)(k0 + kr) * N + colbase + bc];
            *(float4*)&Bs[kr][bc] = bv;
        }
        __syncthreads();
#pragma unroll
        for (int kk = 0; kk < 16; kk++) {
            float4 a0 = *(const float4*)&As[kk][ty * 8];
            float4 a1 = *(const float4*)&As[kk][ty * 8 + 4];
            float4 b0 = *(const float4*)&Bs[kk][tx * 8];
            float4 b1 = *(const float4*)&Bs[kk][tx * 8 + 4];
            float av[8] = {a0.x, a0.y, a0.z, a0.w, a1.x, a1.y, a1.z, a1.w};
            float bv[8] = {b0.x, b0.y, b0.z, b0.w, b1.x, b1.y, b1.z, b1.w};
#pragma unroll
            for (int i = 0; i < 8; i++)
#pragma unroll
                for (int j = 0; j < 8; j++)
                    acc[i][j] += av[i] * bv[j];
        }
        __syncthreads();
    }

#pragma unroll
    for (int i = 0; i < 8; i++) {
        int row = rowbase + ty * 8 + i;
        if (row >= M) continue;
        float4 v0 = make_float4(acc[i][0], acc[i][1], acc[i][2], acc[i][3]);
        float4 v1 = make_float4(acc[i][4], acc[i][5], acc[i][6], acc[i][7]);
        if (idx) {
            const float* ap = add + (size_t)idx[row] * N + colbase + tx * 8;
            float4 a0 = *(const float4*)ap;
            float4 a1 = *(const float4*)(ap + 4);
            v0.x += a0.x; v0.y += a0.y; v0.z += a0.z; v0.w += a0.w;
            v1.x += a1.x; v1.y += a1.y; v1.z += a1.z; v1.w += a1.w;
        }
        *(float4*)&C[(size_t)row * N + colbase + tx * 8]     = v0;
        *(float4*)&C[(size_t)row * N + colbase + tx * 8 + 4] = v1;
    }
}

// ============================ GEMM Mx32 (N=32) ==============================
// C[M,32] = A[M,K] @ B[K,32]; 256 threads, tile 128x32, 4x4/thread. K%16==0.
__global__ void gemm_n32(const float* __restrict__ A, const float* __restrict__ B,
                         float* __restrict__ C, int M, int K) {
    __shared__ float As[16][128];
    __shared__ float Bs[16][32];
    const int t  = threadIdx.x;
    const int tx = t & 7;      // 0..7  (cols tx*4..tx*4+3)
    const int ty = t >> 3;     // 0..31 (rows ty*4..ty*4+3)
    const int rowbase = blockIdx.x * 128;
    const int ar = t >> 2;
    const int ak = (t & 3) * 4;

    float acc[4][4] = {};
    for (int k0 = 0; k0 < K; k0 += 16) {
#pragma unroll
        for (int half = 0; half < 2; half++) {
            int r = ar + half * 64;
            float4 av = make_float4(0.f, 0.f, 0.f, 0.f);
            if (rowbase + r < M)
                av = *(const float4*)&A[(size_t)(rowbase + r) * K + k0 + ak];
            As[ak + 0][r] = av.x; As[ak + 1][r] = av.y;
            As[ak + 2][r] = av.z; As[ak + 3][r] = av.w;
        }
        if (t < 128) {
            int bkr = t >> 3, bcc = (t & 7) * 4;
            *(float4*)&Bs[bkr][bcc] = *(const float4*)&B[(size_t)(k0 + bkr) * 32 + bcc];
        }
        __syncthreads();
#pragma unroll
        for (int kk = 0; kk < 16; kk++) {
            float4 a = *(const float4*)&As[kk][ty * 4];
            float4 b = *(const float4*)&Bs[kk][tx * 4];
            acc[0][0] += a.x * b.x; acc[0][1] += a.x * b.y; acc[0][2] += a.x * b.z; acc[0][3] += a.x * b.w;
            acc[1][0] += a.y * b.x; acc[1][1] += a.y * b.y; acc[1][2] += a.y * b.z; acc[1][3] += a.y * b.w;
            acc[2][0] += a.z * b.x; acc[2][1] += a.z * b.y; acc[2][2] += a.z * b.z; acc[2][3] += a.z * b.w;
            acc[3][0] += a.w * b.x; acc[3][1] += a.w * b.y; acc[3][2] += a.w * b.z; acc[3][3] += a.w * b.w;
        }
        __syncthreads();
    }
#pragma unroll
    for (int i = 0; i < 4; i++) {
        int row = rowbase + ty * 4 + i;
        if (row >= M) continue;
        *(float4*)&C[(size_t)row * 32 + tx * 4] =
            make_float4(acc[i][0], acc[i][1], acc[i][2], acc[i][3]);
    }
}

// ============================ GEMM 64x64x16 (small) =========================
__global__ void gemm64(const float* __restrict__ A, const float* __restrict__ B,
                       float* __restrict__ C, int M, int N, int K) {
    __shared__ float As[16][64];
    __shared__ float Bs[16][64];
    const int t  = threadIdx.x;
    const int tx = t & 15;
    const int ty = t >> 4;
    const int rowbase = blockIdx.y * 64;
    const int colbase = blockIdx.x * 64;
    const int ar = t >> 2;
    const int ak = (t & 3) * 4;
    const int bk = t >> 4;
    const int bc = (t & 15) * 4;

    float acc[4][4] = {};
    for (int k0 = 0; k0 < K; k0 += 16) {
        float4 av = make_float4(0.f, 0.f, 0.f, 0.f);
        if (rowbase + ar < M)
            av = *(const float4*)&A[(size_t)(rowbase + ar) * K + k0 + ak];
        As[ak + 0][ar] = av.x; As[ak + 1][ar] = av.y;
        As[ak + 2][ar] = av.z; As[ak + 3][ar] = av.w;
        float4 bv = make_float4(0.f, 0.f, 0.f, 0.f);
        if (colbase + bc < N)
            bv = *(const float4*)&B[(size_t)(k0 + bk) * N + colbase + bc];
        *(float4*)&Bs[bk][bc] = bv;
        __syncthreads();
#pragma unroll
        for (int kk = 0; kk < 16; kk++) {
            float4 a = *(const float4*)&As[kk][ty * 4];
            float4 b = *(const float4*)&Bs[kk][tx * 4];
            acc[0][0] += a.x * b.x; acc[0][1] += a.x * b.y; acc[0][2] += a.x * b.z; acc[0][3] += a.x * b.w;
            acc[1][0] += a.y * b.x; acc[1][1] += a.y * b.y; acc[1][2] += a.y * b.z; acc[1][3] += a.y * b.w;
            acc[2][0] += a.z * b.x; acc[2][1] += a.z * b.y; acc[2][2] += a.z * b.z; acc[2][3] += a.z * b.w;
            acc[3][0] += a.w * b.x; acc[3][1] += a.w * b.y; acc[3][2] += a.w * b.z; acc[3][3] += a.w * b.w;
        }
        __syncthreads();
    }
#pragma unroll
    for (int i = 0; i < 4; i++) {
        int row = rowbase + ty * 4 + i;
        if (row >= M) continue;
#pragma unroll
        for (int j = 0; j < 4; j++) {
            int col = colbase + tx * 4 + j;
            if (col < N) C[(size_t)row * N + col] = acc[i][j];
        }
    }
}

// ----------------------- attention logits per node --------------------------
__global__ void alpha_warp(const float* __restrict__ h,
                           const float* __restrict__ a_src,
                           const float* __restrict__ a_dst,
                           float* __restrict__ as_out, float* __restrict__ ad_out,
                           int N, int H, int C) {
    int warp = (blockIdx.x * blockDim.x + threadIdx.x) >> 5;
    int lane = threadIdx.x & 31;
    if (warp >= N) return;
    const float* hr = h + (size_t)warp * H * C;
    for (int hh = 0; hh < H; hh++) {
        float s1 = 0.f, s2 = 0.f;
        for (int c = lane; c < C; c += 32) {
            float v = hr[hh * C + c];
            s1 += v * a_src[hh * C + c];
            s2 += v * a_dst[hh * C + c];
        }
#pragma unroll
        for (int o = 16; o; o >>= 1) {
            s1 += __shfl_xor_sync(0xffffffffu, s1, o);
            s2 += __shfl_xor_sync(0xffffffffu, s2, o);
        }
        if (lane == 0) {
            as_out[warp * H + hh] = s1;
            ad_out[warp * H + hh] = s2;
        }
    }
}

// ===================== fused gather: softmax + aggregate =====================
// one warp per (node, head). ACT: 0 = bias, 1 = bias+relu, 2 = bias+log_softmax
template<int H, int C, int ACT>
__global__ void gat_gather(const int* __restrict__ rowptr, const int* __restrict__ colv,
                           const float* __restrict__ as_, const float* __restrict__ ad_,
                           const float* __restrict__ h, const float* __restrict__ bias,
                           float* __restrict__ outbuf, int N) {
    int gw   = (blockIdx.x * blockDim.x + threadIdx.x) >> 5;
    int lane = threadIdx.x & 31;
    if (gw >= N * H) return;
    int n  = gw / H;
    int hh = gw - n * H;

    int start = rowptr[n], end = rowptr[n + 1];
    float adv = ad_[n * H + hh];

    float ssum = 0.f;
    for (int j = start + lane; j < end; j += 32) {
        float v = as_[colv[j] * H + hh] + adv;
        v = (v > 0.f) ? v : 0.2f * v;
        ssum += __expf(v);
    }
#pragma unroll
    for (int o = 16; o; o >>= 1) ssum += __shfl_xor_sync(0xffffffffu, ssum, o);
    float inv = 1.f / (ssum + 1e-16f);

    float acc0 = 0.f, acc1 = 0.f;
    for (int base = start; base < end; base += 32) {
        int jj = base + lane;
        int srcv = 0; float al = 0.f;
        if (jj < end) {
            srcv = colv[jj];
            float v = as_[srcv * H + hh] + adv;
            v = (v > 0.f) ? v : 0.2f * v;
            al = __expf(v);
        }
        int kmax = min(32, end - base);
        for (int k = 0; k < kmax; k++) {
            int   s_k = __shfl_sync(0xffffffffu, srcv, k);
            float a_k = __shfl_sync(0xffffffffu, al,   k);
            const float* hp = h + (size_t)s_k * (H * C) + hh * C;
            acc0 += a_k * hp[lane];
            if (C == 64) acc1 += a_k * hp[lane + 32];
        }
    }

    if (ACT == 2) {
        float v = acc0 * inv + bias[lane];
        float m = v;
#pragma unroll
        for (int o = 16; o; o >>= 1) m = fmaxf(m, __shfl_xor_sync(0xffffffffu, m, o));
        float ex = __expf(v - m);
        float se = ex;
#pragma unroll
        for (int o = 16; o; o >>= 1) se += __shfl_xor_sync(0xffffffffu, se, o);
        outbuf[(size_t)n * 32 + lane] = (v - m) - logf(se);
    } else {
        size_t idx = (size_t)n * (H * C) + hh * C;
        float v0 = acc0 * inv + bias[hh * C + lane];
        if (ACT == 1) v0 = fmaxf(v0, 0.f);
        outbuf[idx + lane] = v0;
        if (C == 64) {
            float v1 = acc1 * inv + bias[hh * C + lane + 32];
            if (ACT == 1) v1 = fmaxf(v1, 0.f);
            outbuf[idx + lane + 32] = v1;
        }
    }
}

// --------------------------------- host side --------------------------------
template<typename T>
static inline T* sym(const void* s) {
    void* p = nullptr;
    cudaGetSymbolAddress(&p, s);
    return (T*)p;
}

extern "C" void kernel_launch(void* const* d_in, const int* in_sizes, int n_in,
                              void* d_out, int out_size) {
    const float* dept_x  = (const float*)d_in[0];
    const int*   dept_ei = (const int*)  d_in[1];
    const float* emp_x   = (const float*)d_in[2];
    const int*   emp_ei  = (const int*)  d_in[3];
    const int*   dept_ix = (const int*)  d_in[4];
    const float* W_d1    = (const float*)d_in[5];
    const float* as_d1   = (const float*)d_in[6];
    const float* ad_d1   = (const float*)d_in[7];
    const float* b_d1    = (const float*)d_in[8];
    const float* W_d2    = (const float*)d_in[9];
    const float* as_d2   = (const float*)d_in[10];
    const float* ad_d2   = (const float*)d_in[11];
    const float* b_d2    = (const float*)d_in[12];
    const float* W_e1    = (const float*)d_in[13];
    const float* as_e1   = (const float*)d_in[14];
    const float* ad_e1   = (const float*)d_in[15];
    const float* b_e1    = (const float*)d_in[16];
    const float* W_e2    = (const float*)d_in[17];
    const float* as_e2   = (const float*)d_in[18];
    const float* ad_e2   = (const float*)d_in[19];
    const float* b_e2    = (const float*)d_in[20];
    float* out = (float*)d_out;

    float *p_d_h1 = sym<float>(g_d_h1), *p_d_as1 = sym<float>(g_d_as1), *p_d_ad1 = sym<float>(g_d_ad1);
    float *p_d_out1 = sym<float>(g_d_out1), *p_d_h2 = sym<float>(g_d_h2);
    float *p_d_as2 = sym<float>(g_d_as2), *p_d_ad2 = sym<float>(g_d_ad2), *p_d_out2 = sym<float>(g_d_out2);
    float *p_dproj = sym<float>(g_dproj);
    float *p_e_h1 = sym<float>(g_e_h1);
    float *p_e_as1 = sym<float>(g_e_as1), *p_e_ad1 = sym<float>(g_e_ad1), *p_e_out1 = sym<float>(g_e_out1);
    float *p_e_h2 = sym<float>(g_e_h2), *p_e_as2 = sym<float>(g_e_as2), *p_e_ad2 = sym<float>(g_e_ad2);

    int *deg_d = sym<int>(g_deg_d), *cur_d = sym<int>(g_cur_d), *row_d = sym<int>(g_row_d);
    int *col_d = sym<int>(g_colv_d), *bs_d = sym<int>(g_bs_d);
    int *deg_e = sym<int>(g_deg_e), *cur_e = sym<int>(g_cur_e), *row_e = sym<int>(g_row_e);
    int *col_e = sym<int>(g_colv_e), *bs_e = sym<int>(g_bs_e);

    const int TB = 256;

    cudaMemsetAsync(deg_d, 0, sizeof(int) * N_D);
    cudaMemsetAsync(cur_d, 0, sizeof(int) * N_D);
    cudaMemsetAsync(deg_e, 0, sizeof(int) * N_E);
    cudaMemsetAsync(cur_e, 0, sizeof(int) * N_E);

    // ---- build CSR: dept graph ----
    {
        int nb = cdiv(N_D, 256);
        deg_count<<<cdiv(E_D, TB), TB>>>(dept_ei, E_D, deg_d);
        block_sum<<<nb, 256>>>(deg_d, N_D, bs_d);
        scan_bsums<<<1, 32>>>(bs_d, nb, row_d, E_D + N_D, N_D);
        scan_final<<<nb, 256>>>(deg_d, bs_d, N_D, row_d);
        fill_csr<<<cdiv(E_D + N_D, TB), TB>>>(dept_ei, E_D, N_D, row_d, cur_d, col_d);
    }
    // ---- build CSR: emp graph ----
    {
        int nb = cdiv(N_E, 256);
        deg_count<<<cdiv(E_E, TB), TB>>>(emp_ei, E_E, deg_e);
        block_sum<<<nb, 256>>>(deg_e, N_E, bs_e);
        scan_bsums<<<1, 32>>>(bs_e, nb, row_e, E_E + N_E, N_E);
        scan_final<<<nb, 256>>>(deg_e, bs_e, N_E, row_e);
        fill_csr<<<cdiv(E_E + N_E, TB), TB>>>(emp_ei, E_E, N_E, row_e, cur_e, col_e);
    }

    // ============ dept layer 1: GAT(128 -> 4x64, concat) + ReLU ============
    {
        dim3 g(cdiv(HEADS * DHC, 128), cdiv(N_D, 128));
        gemm128<<<g, 256>>>(dept_x, W_d1, p_d_h1, N_D, HEADS * DHC, IN_F, nullptr, nullptr);
        alpha_warp<<<cdiv(N_D * 32, TB), TB>>>(p_d_h1, as_d1, ad_d1, p_d_as1, p_d_ad1, N_D, HEADS, DHC);
        gat_gather<HEADS, DHC, 1><<<cdiv(N_D * HEADS * 32, TB), TB>>>(
            row_d, col_d, p_d_as1, p_d_ad1, p_d_h1, b_d1, p_d_out1, N_D);
    }
    // ============ dept layer 2: GAT(256 -> 64, heads=1) ============
    {
        dim3 g(cdiv(DHC, 64), cdiv(N_D, 64));
        gemm64<<<g, 256>>>(p_d_out1, W_d2, p_d_h2, N_D, DHC, HEADS * DHC);
        alpha_warp<<<cdiv(N_D * 32, TB), TB>>>(p_d_h2, as_d2, ad_d2, p_d_as2, p_d_ad2, N_D, 1, DHC);
        gat_gather<1, DHC, 0><<<cdiv(N_D * 32, TB), TB>>>(
            row_d, col_d, p_d_as2, p_d_ad2, p_d_h2, b_d2, p_d_out2, N_D);
    }
    // ============ dproj = d_out2 @ W_e1[128:, :]  (2000 x 256, K=64) ============
    {
        dim3 g(cdiv(HEADS * EHC, 128), cdiv(N_D, 128));
        gemm128<<<g, 256>>>(p_d_out2, W_e1 + (size_t)IN_F * HEADS * EHC, p_dproj,
                            N_D, HEADS * EHC, DHC, nullptr, nullptr);
    }
    // ============ emp layer 1: h1 = emp_x @ W_e1[:128,:] + dproj[dept_idx] ======
    {
        dim3 g(cdiv(HEADS * EHC, 128), cdiv(N_E, 128));
        gemm128<<<g, 256>>>(emp_x, W_e1, p_e_h1, N_E, HEADS * EHC, IN_F, p_dproj, dept_ix);
        alpha_warp<<<cdiv(N_E * 32, TB), TB>>>(p_e_h1, as_e1, ad_e1, p_e_as1, p_e_ad1, N_E, HEADS, EHC);
        gat_gather<HEADS, EHC, 1><<<cdiv(N_E * HEADS * 32, TB), TB>>>(
            row_e, col_e, p_e_as1, p_e_ad1, p_e_h1, b_e1, p_e_out1, N_E);
    }
    // ============ emp layer 2: GAT(256 -> 32) + log_softmax ============
    {
        gemm_n32<<<cdiv(N_E, 128), 256>>>(p_e_out1, W_e2, p_e_h2, N_E, HEADS * EHC);
        alpha_warp<<<cdiv(N_E * 32, TB), TB>>>(p_e_h2, as_e2, ad_e2, p_e_as2, p_e_ad2, N_E, 1, OUTC);
        gat_gather<1, OUTC, 2><<<cdiv(N_E * 32, TB), TB>>>(
            row_e, col_e, p_e_as2, p_e_ad2, p_e_h2, b_e2, out, N_E);
    }
}